// round 1
// baseline (speedup 1.0000x reference)
#include <cuda_runtime.h>
#include <math.h>

#define B_SZ 8
#define LSEQ 200
#define DM   256
#define DI   512
#define DS   64
#define DTR  16
#define NB   4
#define MROWS (B_SZ*LSEQ)      /* 1600 */
#define XP_N  (DTR + 2*DS)     /* 144  */

/* ---------------- scratch (device globals; no runtime allocation) -------- */
__device__ float g_xz[MROWS * 2 * DI];   /* x @ W_in : [1600][1024]          */
__device__ float g_xm[MROWS * DI];       /* conv+silu(x_m)                   */
__device__ float g_xp[MROWS * XP_N];     /* x_m @ W_x (+phase on C region)   */
__device__ float g_dt[MROWS * DI];       /* dt after softplus & modulation   */
__device__ float g_y [MROWS * DI];       /* scan output, gated               */
__device__ float g_o [MROWS * DM];       /* y @ W_out (pre-residual/LN)      */

__device__ __forceinline__ float softplusf(float x) {
    return x > 20.f ? x : log1pf(__expf(x));
}
__device__ __forceinline__ float siluf(float x) {
    return x / (1.f + __expf(-x));
}

/* ---------------- generic 64x64x16 register-tiled fp32 GEMM -------------- */
/* C[M,N] = A[M,K] @ B[K,N], row-major, 256 threads, 4x4 micro-tile.        */
__device__ __forceinline__ void gemm_body(const float* __restrict__ A,
                                          const float* __restrict__ B,
                                          float* __restrict__ C,
                                          int M, int N, int K) {
    __shared__ float As[16][65];   /* padded: kill store bank conflicts */
    __shared__ float Bs[16][64];

    const int tx = threadIdx.x & 15;   /* col group */
    const int ty = threadIdx.x >> 4;   /* row group */
    const int rowBase = blockIdx.y * 64;
    const int colBase = blockIdx.x * 64;

    float acc[4][4];
#pragma unroll
    for (int i = 0; i < 4; i++)
#pragma unroll
        for (int j = 0; j < 4; j++) acc[i][j] = 0.f;

    for (int k0 = 0; k0 < K; k0 += 16) {
#pragma unroll
        for (int i = 0; i < 4; i++) {
            int idx = threadIdx.x + i * 256;          /* 0..1023 */
            /* A tile: 64 rows x 16 k */
            int m  = idx >> 4;
            int kk = idx & 15;
            int gr = rowBase + m, gk = k0 + kk;
            As[kk][m] = (gr < M && gk < K) ? A[gr * K + gk] : 0.f;
            /* B tile: 16 k x 64 cols */
            int kk2 = idx >> 6;
            int n   = idx & 63;
            int gc  = colBase + n, gk2 = k0 + kk2;
            Bs[kk2][n] = (gk2 < K && gc < N) ? B[gk2 * N + gc] : 0.f;
        }
        __syncthreads();
#pragma unroll
        for (int kk = 0; kk < 16; kk++) {
            float a[4], bv[4];
#pragma unroll
            for (int i = 0; i < 4; i++) a[i]  = As[kk][ty * 4 + i];
#pragma unroll
            for (int j = 0; j < 4; j++) bv[j] = Bs[kk][tx * 4 + j];
#pragma unroll
            for (int i = 0; i < 4; i++)
#pragma unroll
                for (int j = 0; j < 4; j++) acc[i][j] += a[i] * bv[j];
        }
        __syncthreads();
    }

#pragma unroll
    for (int i = 0; i < 4; i++) {
        int r = rowBase + ty * 4 + i;
        if (r >= M) continue;
#pragma unroll
        for (int j = 0; j < 4; j++) {
            int c = colBase + tx * 4 + j;
            if (c < N) C[r * N + c] = acc[i][j];
        }
    }
}

__global__ void gemm_xz_kernel(const float* __restrict__ x,
                               const float* __restrict__ W_in) {
    gemm_body(x, W_in, g_xz, MROWS, 2 * DI, DM);
}
__global__ void gemm_xp_kernel(const float* __restrict__ W_x) {
    gemm_body(g_xm, W_x, g_xp, MROWS, XP_N, DI);
}
__global__ void gemm_out_kernel(const float* __restrict__ W_out) {
    gemm_body(g_y, W_out, g_o, MROWS, DM, DI);
}

/* ---------------- depthwise causal conv (k=4) + SiLU --------------------- */
__global__ void conv_silu_kernel(const float* __restrict__ conv_w,
                                 const float* __restrict__ conv_b) {
    int idx = blockIdx.x * blockDim.x + threadIdx.x;
    if (idx >= MROWS * DI) return;
    int d = idx % DI;
    int l = (idx / DI) % LSEQ;
    int b = idx / (DI * LSEQ);
    float acc = conv_b[d];
#pragma unroll
    for (int k = 0; k < 4; k++) {
        int li = l - 3 + k;
        if (li >= 0)
            acc += conv_w[d * 4 + k] * g_xz[(b * LSEQ + li) * (2 * DI) + d];
    }
    g_xm[idx] = siluf(acc);
}

/* ---------------- C_st += phase_feats @ W_phase -------------------------- */
__global__ void phase_add_kernel(const float* __restrict__ cos_phi,
                                 const float* __restrict__ sin_phi,
                                 const float* __restrict__ W_phase) {
    int idx = blockIdx.x * blockDim.x + threadIdx.x;  /* row*64 + n */
    if (idx >= MROWS * DS) return;
    int n = idx % DS;
    int row = idx / DS;
    int b = row / LSEQ, l = row % LSEQ;
    float acc = 0.f;
#pragma unroll
    for (int j = 0; j < NB; j++) {
        acc += cos_phi[(b * NB + j) * LSEQ + l] * W_phase[j * DS + n];
        acc += sin_phi[(b * NB + j) * LSEQ + l] * W_phase[(j + NB) * DS + n];
    }
    g_xp[row * XP_N + DTR + DS + n] += acc;
}

/* ---------------- dt = softplus(dt_lr@W_dt + b) * (1+softplus(dmm)) ------ */
__global__ void dt_kernel(const float* __restrict__ W_dt,
                          const float* __restrict__ b_dt,
                          const float* __restrict__ delta_mag) {
    int idx = blockIdx.x * blockDim.x + threadIdx.x;  /* row*512 + d */
    if (idx >= MROWS * DI) return;
    int d = idx % DI;
    int row = idx / DI;
    int b = row / LSEQ, l = row % LSEQ;
    const float* dl = &g_xp[row * XP_N];
    float acc = b_dt[d];
#pragma unroll
    for (int r = 0; r < DTR; r++)
        acc += dl[r] * W_dt[r * DI + d];
    float dmm = 0.25f * (delta_mag[(b * NB + 0) * LSEQ + l] +
                         delta_mag[(b * NB + 1) * LSEQ + l] +
                         delta_mag[(b * NB + 2) * LSEQ + l] +
                         delta_mag[(b * NB + 3) * LSEQ + l]);
    g_dt[idx] = softplusf(acc) * (1.f + softplusf(dmm));
}

/* ---------------- selective scan: 1 warp per (b,d); 2 states/lane -------- */
__global__ void scan_kernel(const float* __restrict__ A_log,
                            const float* __restrict__ D_skip) {
    int warp = (blockIdx.x * blockDim.x + threadIdx.x) >> 5;
    int lane = threadIdx.x & 31;
    if (warp >= B_SZ * DI) return;
    int b = warp / DI, d = warp % DI;

    float A0 = -__expf(A_log[d * DS + lane]);
    float A1 = -__expf(A_log[d * DS + lane + 32]);
    float Dd = D_skip[d];
    float h0 = 0.f, h1 = 0.f;

    int rowBase = b * LSEQ;
    for (int t = 0; t < LSEQ; t++) {
        int row = rowBase + t;
        float dtv = g_dt[row * DI + d];      /* uniform across warp */
        float u   = g_xm[row * DI + d];
        const float* xpr = &g_xp[row * XP_N];
        float Bv0 = xpr[DTR + lane];
        float Bv1 = xpr[DTR + 32 + lane];
        float Cv0 = xpr[DTR + DS + lane];
        float Cv1 = xpr[DTR + DS + 32 + lane];

        float du = dtv * u;
        h0 = __expf(dtv * A0) * h0 + du * Bv0;
        h1 = __expf(dtv * A1) * h1 + du * Bv1;

        float y = h0 * Cv0 + h1 * Cv1;
#pragma unroll
        for (int off = 16; off; off >>= 1)
            y += __shfl_xor_sync(0xffffffffu, y, off);

        if (lane == 0) {
            float z = g_xz[row * (2 * DI) + DI + d];
            g_y[row * DI + d] = (y + u * Dd) * siluf(z);
        }
    }
}

/* ---------------- residual add + LayerNorm (two-pass variance) ----------- */
__global__ void ln_kernel(const float* __restrict__ x,
                          const float* __restrict__ gamma,
                          const float* __restrict__ beta,
                          float* __restrict__ out) {
    int row = blockIdx.x;
    int c = threadIdx.x;
    float v = g_o[row * DM + c] + x[row * DM + c];

    __shared__ float sbuf[DM];
    sbuf[c] = v;
    __syncthreads();
    for (int s = 128; s > 0; s >>= 1) {
        if (c < s) sbuf[c] += sbuf[c + s];
        __syncthreads();
    }
    float mu = sbuf[0] * (1.f / DM);
    __syncthreads();

    float dv = v - mu;
    sbuf[c] = dv * dv;
    __syncthreads();
    for (int s = 128; s > 0; s >>= 1) {
        if (c < s) sbuf[c] += sbuf[c + s];
        __syncthreads();
    }
    float var = sbuf[0] * (1.f / DM);
    out[row * DM + c] = dv * rsqrtf(var + 1e-12f) * gamma[c] + beta[c];
}

/* ---------------- launch --------------------------------------------------*/
extern "C" void kernel_launch(void* const* d_in, const int* in_sizes, int n_in,
                              void* d_out, int out_size) {
    const float* x         = (const float*)d_in[0];
    const float* cos_phi   = (const float*)d_in[1];
    const float* sin_phi   = (const float*)d_in[2];
    const float* delta_mag = (const float*)d_in[3];
    const float* W_in      = (const float*)d_in[4];
    const float* conv_w    = (const float*)d_in[5];
    const float* conv_b    = (const float*)d_in[6];
    const float* W_x       = (const float*)d_in[7];
    const float* W_dt      = (const float*)d_in[8];
    const float* b_dt      = (const float*)d_in[9];
    const float* A_log     = (const float*)d_in[10];
    const float* D_skip    = (const float*)d_in[11];
    const float* W_out     = (const float*)d_in[12];
    const float* gamma     = (const float*)d_in[13];
    const float* beta      = (const float*)d_in[14];
    const float* W_phase   = (const float*)d_in[15];
    float* out = (float*)d_out;

    /* 1) xz = x @ W_in : 1600x256 @ 256x1024 */
    gemm_xz_kernel<<<dim3((2 * DI) / 64, MROWS / 64), 256>>>(x, W_in);

    /* 2) depthwise causal conv + SiLU -> g_xm */
    conv_silu_kernel<<<(MROWS * DI + 255) / 256, 256>>>(conv_w, conv_b);

    /* 3) xp = x_m @ W_x : 1600x512 @ 512x144 (N masked) */
    gemm_xp_kernel<<<dim3((XP_N + 63) / 64, MROWS / 64), 256>>>(W_x);

    /* 4) C_st += phase_feats @ W_phase */
    phase_add_kernel<<<(MROWS * DS + 255) / 256, 256>>>(cos_phi, sin_phi, W_phase);

    /* 5) dt */
    dt_kernel<<<(MROWS * DI + 255) / 256, 256>>>(W_dt, b_dt, delta_mag);

    /* 6) selective scan + D-skip + z-gate -> g_y */
    scan_kernel<<<(B_SZ * DI * 32 + 255) / 256, 256>>>(A_log, D_skip);

    /* 7) g_o = g_y @ W_out : 1600x512 @ 512x256 */
    gemm_out_kernel<<<dim3(DM / 64, MROWS / 64), 256>>>(W_out);

    /* 8) residual + LayerNorm -> out */
    ln_kernel<<<MROWS, DM>>>(x, gamma, beta, out);
}

// round 2
// speedup vs baseline: 1.2915x; 1.2915x over previous
#include <cuda_runtime.h>
#include <math.h>

#define B_SZ 8
#define LSEQ 200
#define DM   256
#define DI   512
#define DS   64
#define DTR  16
#define NB   4
#define MROWS (B_SZ*LSEQ)      /* 1600 */
#define XP_N  (DTR + 2*DS)     /* 144 real columns  */
#define XP_P  192              /* padded stride (3x64 tiles, no guards) */

/* ---------------- scratch (device globals; no runtime allocation) -------- */
__device__ float g_xz[MROWS * 2 * DI];   /* x @ W_in : [1600][1024]          */
__device__ float g_xm[MROWS * DI];       /* conv+silu(x_m)                   */
__device__ float g_xp[MROWS * XP_P];     /* x_m @ W_x (+phase), padded       */
__device__ float g_dt[MROWS * DI];       /* dt after softplus & modulation   */
__device__ float g_y [MROWS * DI];       /* scan output, gated               */
__device__ float g_o [MROWS * DM];       /* y @ W_out (pre-residual/LN)      */

__device__ __forceinline__ float softplusf(float x) {
    return x > 20.f ? x : log1pf(__expf(x));
}
__device__ __forceinline__ float siluf(float x) {
    return x / (1.f + __expf(-x));
}
__device__ __forceinline__ float warp_sum(float v) {
#pragma unroll
    for (int o = 16; o; o >>= 1) v += __shfl_xor_sync(0xffffffffu, v, o);
    return v;
}

/* ---------------- 64x64x16 fp32 GEMM, float4 everywhere ------------------ */
/* C[M,N] = A[M,K] @ B[K,N]. M%64==0, K%16==0. GUARDN: N not mult of 64     */
/* (B reads guarded, stores go to padded ldc). PHASE: fuse C_st phase add.  */
template<bool GUARDN, bool PHASE>
__global__ __launch_bounds__(256) void gemm64_kernel(
    const float* __restrict__ A, const float* __restrict__ B,
    float* __restrict__ C, int M, int N, int K, int ldc,
    const float* __restrict__ cosp, const float* __restrict__ sinp,
    const float* __restrict__ Wph)
{
    __shared__ float As[16][68];   /* transposed A tile; row stride 272B (16B mult) */
    __shared__ float Bs[16][64];

    const int tid = threadIdx.x;
    const int tx = tid & 15, ty = tid >> 4;
    const int rowBase = blockIdx.y * 64;
    const int colBase = blockIdx.x * 64;

    float acc[4][4] = {};

    const int arow = tid >> 2;          /* 0..63 */
    const int akq  = (tid & 3) * 4;     /* k offset 0/4/8/12 */
    const int bkk  = tid >> 4;          /* 0..15 */
    const int bnq  = (tid & 15) * 4;    /* n offset */

    for (int k0 = 0; k0 < K; k0 += 16) {
        float4 av = *(const float4*)(A + (rowBase + arow) * K + k0 + akq);
        As[akq + 0][arow] = av.x;
        As[akq + 1][arow] = av.y;
        As[akq + 2][arow] = av.z;
        As[akq + 3][arow] = av.w;

        if (!GUARDN) {
            *(float4*)&Bs[bkk][bnq] =
                *(const float4*)(B + (k0 + bkk) * N + colBase + bnq);
        } else {
            const float* brow = B + (k0 + bkk) * N;
            int gc = colBase + bnq;
            Bs[bkk][bnq + 0] = (gc + 0 < N) ? brow[gc + 0] : 0.f;
            Bs[bkk][bnq + 1] = (gc + 1 < N) ? brow[gc + 1] : 0.f;
            Bs[bkk][bnq + 2] = (gc + 2 < N) ? brow[gc + 2] : 0.f;
            Bs[bkk][bnq + 3] = (gc + 3 < N) ? brow[gc + 3] : 0.f;
        }
        __syncthreads();

#pragma unroll
        for (int kk = 0; kk < 16; kk++) {
            float4 a4 = *(const float4*)&As[kk][ty * 4];
            float4 b4 = *(const float4*)&Bs[kk][tx * 4];
            float ar[4] = {a4.x, a4.y, a4.z, a4.w};
            float br[4] = {b4.x, b4.y, b4.z, b4.w};
#pragma unroll
            for (int i = 0; i < 4; i++)
#pragma unroll
                for (int j = 0; j < 4; j++) acc[i][j] += ar[i] * br[j];
        }
        __syncthreads();
    }

    const bool doph = PHASE && (colBase < 144) && (colBase + 63 >= 80);

#pragma unroll
    for (int i = 0; i < 4; i++) {
        int r = rowBase + ty * 4 + i;
        float ph[8];
        if (doph) {
            int bb = r / LSEQ, l = r % LSEQ;
#pragma unroll
            for (int jb = 0; jb < NB; jb++) {
                ph[jb]      = cosp[(bb * NB + jb) * LSEQ + l];
                ph[NB + jb] = sinp[(bb * NB + jb) * LSEQ + l];
            }
        }
#pragma unroll
        for (int j = 0; j < 4; j++) {
            int c = colBase + tx * 4 + j;
            float v = acc[i][j];
            if (doph && c >= (DTR + DS) && c < XP_N) {
                int n = c - (DTR + DS);
#pragma unroll
                for (int q = 0; q < 2 * NB; q++) v += ph[q] * Wph[q * DS + n];
            }
            C[r * ldc + c] = v;
        }
    }
}

/* ---------------- depthwise causal conv (k=4) + SiLU --------------------- */
__global__ void conv_silu_kernel(const float* __restrict__ conv_w,
                                 const float* __restrict__ conv_b) {
    int idx = blockIdx.x * blockDim.x + threadIdx.x;
    if (idx >= MROWS * DI) return;
    int d = idx % DI;
    int l = (idx / DI) % LSEQ;
    int b = idx / (DI * LSEQ);
    float acc = conv_b[d];
#pragma unroll
    for (int k = 0; k < 4; k++) {
        int li = l - 3 + k;
        if (li >= 0)
            acc += conv_w[d * 4 + k] * g_xz[(b * LSEQ + li) * (2 * DI) + d];
    }
    g_xm[idx] = siluf(acc);
}

/* ---------------- dt = softplus(dt_lr@W_dt + b) * (1+softplus(dmm)) ------ */
__global__ void dt_kernel(const float* __restrict__ W_dt,
                          const float* __restrict__ b_dt,
                          const float* __restrict__ delta_mag) {
    int idx = blockIdx.x * blockDim.x + threadIdx.x;  /* row*512 + d */
    if (idx >= MROWS * DI) return;
    int d = idx % DI;
    int row = idx / DI;
    int b = row / LSEQ, l = row % LSEQ;
    const float* dl = &g_xp[row * XP_P];
    float acc = b_dt[d];
#pragma unroll
    for (int r = 0; r < DTR; r++)
        acc += dl[r] * W_dt[r * DI + d];
    float dmm = 0.25f * (delta_mag[(b * NB + 0) * LSEQ + l] +
                         delta_mag[(b * NB + 1) * LSEQ + l] +
                         delta_mag[(b * NB + 2) * LSEQ + l] +
                         delta_mag[(b * NB + 3) * LSEQ + l]);
    g_dt[idx] = softplusf(acc) * (1.f + softplusf(dmm));
}

/* ---------------- selective scan: 1 warp per (b,d); prefetched ----------- */
__global__ void scan_kernel(const float* __restrict__ A_log,
                            const float* __restrict__ D_skip) {
    int warp = (blockIdx.x * blockDim.x + threadIdx.x) >> 5;
    int lane = threadIdx.x & 31;
    if (warp >= B_SZ * DI) return;
    int b = warp >> 9, d = warp & (DI - 1);

    float A0 = -__expf(A_log[d * DS + lane]);
    float A1 = -__expf(A_log[d * DS + 32 + lane]);
    float Dd = D_skip[d];
    float h0 = 0.f, h1 = 0.f;

    const float* xp  = g_xp + (size_t)(b * LSEQ) * XP_P;
    const float* dtp = g_dt + (size_t)(b * LSEQ) * DI + d;
    const float* xmp = g_xm + (size_t)(b * LSEQ) * DI + d;
    const float* zp  = g_xz + (size_t)(b * LSEQ) * (2 * DI) + DI + d;
    float* yp        = g_y  + (size_t)(b * LSEQ) * DI + d;

    /* prefetch t = 0 */
    float dtv = dtp[0];
    float u   = xmp[0];
    float B0 = xp[DTR + lane],      B1 = xp[DTR + 32 + lane];
    float C0 = xp[DTR + DS + lane], C1 = xp[DTR + DS + 32 + lane];

    for (int t = 0; t < LSEQ; t++) {
        float dt_c = dtv, u_c = u;
        float B0c = B0, B1c = B1, C0c = C0, C1c = C1;
        if (t + 1 < LSEQ) {   /* prefetch next step while computing this one */
            const float* xpn = xp + (t + 1) * XP_P;
            dtv = dtp[(t + 1) * DI];
            u   = xmp[(t + 1) * DI];
            B0 = xpn[DTR + lane];      B1 = xpn[DTR + 32 + lane];
            C0 = xpn[DTR + DS + lane]; C1 = xpn[DTR + DS + 32 + lane];
        }
        float du = dt_c * u_c;
        h0 = __expf(dt_c * A0) * h0 + du * B0c;
        h1 = __expf(dt_c * A1) * h1 + du * B1c;

        float y = warp_sum(h0 * C0c + h1 * C1c);

        if (lane == 0) {
            float z = zp[t * (2 * DI)];
            yp[t * DI] = (y + u_c * Dd) * siluf(z);
        }
    }
}

/* ---------------- residual add + LayerNorm (single pass) ----------------- */
__global__ void ln_kernel(const float* __restrict__ x,
                          const float* __restrict__ gamma,
                          const float* __restrict__ beta,
                          float* __restrict__ out) {
    int row = blockIdx.x;
    int c = threadIdx.x;
    float v = g_o[row * DM + c] + x[row * DM + c];

    float s  = warp_sum(v);
    float s2 = warp_sum(v * v);
    __shared__ float ws[8], ws2[8];
    int w = c >> 5, lane = c & 31;
    if (lane == 0) { ws[w] = s; ws2[w] = s2; }
    __syncthreads();
    float tot = 0.f, tot2 = 0.f;
#pragma unroll
    for (int i = 0; i < 8; i++) { tot += ws[i]; tot2 += ws2[i]; }
    float mu  = tot * (1.f / DM);
    float var = tot2 * (1.f / DM) - mu * mu;
    out[row * DM + c] = (v - mu) * rsqrtf(var + 1e-12f) * gamma[c] + beta[c];
}

/* ---------------- launch --------------------------------------------------*/
extern "C" void kernel_launch(void* const* d_in, const int* in_sizes, int n_in,
                              void* d_out, int out_size) {
    const float* x         = (const float*)d_in[0];
    const float* cos_phi   = (const float*)d_in[1];
    const float* sin_phi   = (const float*)d_in[2];
    const float* delta_mag = (const float*)d_in[3];
    const float* W_in      = (const float*)d_in[4];
    const float* conv_w    = (const float*)d_in[5];
    const float* conv_b    = (const float*)d_in[6];
    const float* W_x       = (const float*)d_in[7];
    const float* W_dt      = (const float*)d_in[8];
    const float* b_dt      = (const float*)d_in[9];
    const float* A_log     = (const float*)d_in[10];
    const float* D_skip    = (const float*)d_in[11];
    const float* W_out     = (const float*)d_in[12];
    const float* gamma     = (const float*)d_in[13];
    const float* beta      = (const float*)d_in[14];
    const float* W_phase   = (const float*)d_in[15];
    float* out = (float*)d_out;

    float* pxz; cudaGetSymbolAddress((void**)&pxz, g_xz);
    float* pxm; cudaGetSymbolAddress((void**)&pxm, g_xm);
    float* pxp; cudaGetSymbolAddress((void**)&pxp, g_xp);
    float* py;  cudaGetSymbolAddress((void**)&py,  g_y);
    float* po;  cudaGetSymbolAddress((void**)&po,  g_o);

    /* 1) xz = x @ W_in : 1600x256 @ 256x1024 */
    gemm64_kernel<false,false><<<dim3(16, 25), 256>>>(
        x, W_in, pxz, MROWS, 2 * DI, DM, 2 * DI, nullptr, nullptr, nullptr);

    /* 2) depthwise causal conv + SiLU -> g_xm */
    conv_silu_kernel<<<(MROWS * DI + 255) / 256, 256>>>(conv_w, conv_b);

    /* 3) xp = x_m @ W_x (N=144, padded store) + fused phase add on C cols */
    gemm64_kernel<true,true><<<dim3(3, 25), 256>>>(
        pxm, W_x, pxp, MROWS, XP_N, DI, XP_P, cos_phi, sin_phi, W_phase);

    /* 4) dt */
    dt_kernel<<<(MROWS * DI + 255) / 256, 256>>>(W_dt, b_dt, delta_mag);

    /* 5) selective scan + D-skip + z-gate -> g_y */
    scan_kernel<<<(B_SZ * DI * 32 + 255) / 256, 256>>>(A_log, D_skip);

    /* 6) g_o = g_y @ W_out : 1600x512 @ 512x256 */
    gemm64_kernel<false,false><<<dim3(4, 25), 256>>>(
        py, W_out, po, MROWS, DM, DI, DM, nullptr, nullptr, nullptr);

    /* 7) residual + LayerNorm -> out */
    ln_kernel<<<MROWS, DM>>>(x, gamma, beta, out);
}

// round 3
// speedup vs baseline: 1.5101x; 1.1693x over previous
#include <cuda_runtime.h>
#include <math.h>

#define B_SZ 8
#define LSEQ 200
#define DM   256
#define DI   512
#define DS   64
#define DTR  16
#define NB   4
#define MROWS (B_SZ*LSEQ)      /* 1600 */
#define XP_N  (DTR + 2*DS)     /* 144 real columns  */
#define XP_P  192              /* padded stride     */
#define OSPLIT 4               /* splitK for the out GEMM */

/* ---------------- scratch (device globals; no runtime allocation) -------- */
__device__ float g_xz[MROWS * 2 * DI];        /* x @ W_in                    */
__device__ float g_xm[MROWS * DI];            /* conv+silu(x_m)              */
__device__ float g_xp[MROWS * XP_P];          /* x_m @ W_x (+phase), padded  */
__device__ float g_dt[MROWS * DI];            /* dt                          */
__device__ float g_y [MROWS * DI];            /* scan output, gated          */
__device__ float g_o [OSPLIT * MROWS * DM];   /* splitK slices of y @ W_out  */

__device__ __forceinline__ float softplusf(float x) {
    return x > 20.f ? x : log1pf(__expf(x));
}
__device__ __forceinline__ float siluf(float x) {
    return x / (1.f + __expf(-x));
}
__device__ __forceinline__ float warp_sum(float v) {
#pragma unroll
    for (int o = 16; o; o >>= 1) v += __shfl_xor_sync(0xffffffffu, v, o);
    return v;
}

/* ------------- 64x64x16 fp32 GEMM, double-buffered, splitK-aware --------- */
/* C slice [M,N] = A[:, z*kLen : (z+1)*kLen] @ B[z*kLen:.., :].              */
/* GUARDN: N not multiple of 64 (B loads guarded; stores padded via ldc).    */
/* PHASE : fuse C_st phase-features add into epilogue.                       */
template<bool GUARDN, bool PHASE>
__global__ __launch_bounds__(256) void gemm64_kernel(
    const float* __restrict__ A, int lda,
    const float* __restrict__ B, int ldb,
    float* __restrict__ C, int ldc,
    int N, int kLen, int sliceElems,
    const float* __restrict__ cosp, const float* __restrict__ sinp,
    const float* __restrict__ Wph)
{
    __shared__ float As[2][16][68];
    __shared__ float Bs[2][16][64];

    const int tid = threadIdx.x;
    const int tx = tid & 15, ty = tid >> 4;
    const int rowBase = blockIdx.y * 64;
    const int colBase = blockIdx.x * 64;

    A += (size_t)blockIdx.z * kLen;          /* column offset into A */
    B += (size_t)blockIdx.z * kLen * ldb;    /* row offset into B    */
    C += (size_t)blockIdx.z * sliceElems;

    const int arow = tid >> 2;          /* 0..63  */
    const int akq  = (tid & 3) * 4;     /* 0/4/8/12 */
    const int bkk  = tid >> 4;          /* 0..15  */
    const int bnq  = (tid & 15) * 4;

    float acc[4][4] = {};
    float4 av, bv;

    auto loadG = [&](int k0) {
        av = *(const float4*)(A + (size_t)(rowBase + arow) * lda + k0 + akq);
        if (!GUARDN) {
            bv = *(const float4*)(B + (size_t)(k0 + bkk) * ldb + colBase + bnq);
        } else {
            const float* br = B + (size_t)(k0 + bkk) * ldb;
            int gc = colBase + bnq;
            bv.x = (gc + 0 < N) ? br[gc + 0] : 0.f;
            bv.y = (gc + 1 < N) ? br[gc + 1] : 0.f;
            bv.z = (gc + 2 < N) ? br[gc + 2] : 0.f;
            bv.w = (gc + 3 < N) ? br[gc + 3] : 0.f;
        }
    };
    auto stageS = [&](int s) {
        As[s][akq + 0][arow] = av.x;
        As[s][akq + 1][arow] = av.y;
        As[s][akq + 2][arow] = av.z;
        As[s][akq + 3][arow] = av.w;
        *(float4*)&Bs[s][bkk][bnq] = bv;
    };

    const int nt = kLen / 16;
    loadG(0);
    stageS(0);
    __syncthreads();

    for (int kt = 0; kt < nt; kt++) {
        const int cur = kt & 1;
        if (kt + 1 < nt) loadG((kt + 1) * 16);
#pragma unroll
        for (int kk = 0; kk < 16; kk++) {
            float4 a4 = *(const float4*)&As[cur][kk][ty * 4];
            float4 b4 = *(const float4*)&Bs[cur][kk][tx * 4];
            float ar[4] = {a4.x, a4.y, a4.z, a4.w};
            float br[4] = {b4.x, b4.y, b4.z, b4.w};
#pragma unroll
            for (int i = 0; i < 4; i++)
#pragma unroll
                for (int j = 0; j < 4; j++) acc[i][j] += ar[i] * br[j];
        }
        if (kt + 1 < nt) stageS(cur ^ 1);
        __syncthreads();
    }

    const bool doph = PHASE && (colBase + 63 >= DTR + DS) && (colBase < XP_N);

#pragma unroll
    for (int i = 0; i < 4; i++) {
        int r = rowBase + ty * 4 + i;
        float ph[8];
        if (doph) {
            int bb = r / LSEQ, l = r % LSEQ;
#pragma unroll
            for (int jb = 0; jb < NB; jb++) {
                ph[jb]      = cosp[(bb * NB + jb) * LSEQ + l];
                ph[NB + jb] = sinp[(bb * NB + jb) * LSEQ + l];
            }
        }
#pragma unroll
        for (int j = 0; j < 4; j++) {
            int c = colBase + tx * 4 + j;
            float v = acc[i][j];
            if (doph && c >= (DTR + DS) && c < XP_N) {
                int n = c - (DTR + DS);
#pragma unroll
                for (int q = 0; q < 2 * NB; q++) v += ph[q] * Wph[q * DS + n];
            }
            C[(size_t)r * ldc + c] = v;
        }
    }
}

/* ---------------- depthwise causal conv (k=4) + SiLU --------------------- */
__global__ void conv_silu_kernel(const float* __restrict__ conv_w,
                                 const float* __restrict__ conv_b) {
    int idx = blockIdx.x * blockDim.x + threadIdx.x;
    if (idx >= MROWS * DI) return;
    int d = idx % DI;
    int l = (idx / DI) % LSEQ;
    int b = idx / (DI * LSEQ);
    float4 cw = *(const float4*)(conv_w + d * 4);
    float w[4] = {cw.x, cw.y, cw.z, cw.w};
    float acc = conv_b[d];
#pragma unroll
    for (int k = 0; k < 4; k++) {
        int li = l - 3 + k;
        if (li >= 0)
            acc += w[k] * g_xz[(size_t)(b * LSEQ + li) * (2 * DI) + d];
    }
    g_xm[idx] = siluf(acc);
}

/* -------- dt = softplus(dt_lr@W_dt + b)*(1+softplus(dmm)), 4 d per thread -*/
__global__ __launch_bounds__(256) void dt_kernel(
    const float* __restrict__ W_dt, const float* __restrict__ b_dt,
    const float* __restrict__ delta_mag) {
    /* block = 2 rows; thread handles 4 consecutive d */
    int row = blockIdx.x * 2 + (threadIdx.x >> 7);
    int d0  = (threadIdx.x & 127) * 4;
    int b = row / LSEQ, l = row % LSEQ;

    float dl[DTR];
    {
        const float4* p = (const float4*)(g_xp + (size_t)row * XP_P);
#pragma unroll
        for (int q = 0; q < DTR / 4; q++) {
            float4 v = p[q];
            dl[q * 4 + 0] = v.x; dl[q * 4 + 1] = v.y;
            dl[q * 4 + 2] = v.z; dl[q * 4 + 3] = v.w;
        }
    }
    float4 acc = *(const float4*)(b_dt + d0);
#pragma unroll
    for (int r = 0; r < DTR; r++) {
        float4 w = *(const float4*)(W_dt + r * DI + d0);
        acc.x += dl[r] * w.x;  acc.y += dl[r] * w.y;
        acc.z += dl[r] * w.z;  acc.w += dl[r] * w.w;
    }
    float dmm = 0.25f * (delta_mag[(b * NB + 0) * LSEQ + l] +
                         delta_mag[(b * NB + 1) * LSEQ + l] +
                         delta_mag[(b * NB + 2) * LSEQ + l] +
                         delta_mag[(b * NB + 3) * LSEQ + l]);
    float scale = 1.f + softplusf(dmm);
    float4 o;
    o.x = softplusf(acc.x) * scale;
    o.y = softplusf(acc.y) * scale;
    o.z = softplusf(acc.z) * scale;
    o.w = softplusf(acc.w) * scale;
    *(float4*)(g_dt + (size_t)row * DI + d0) = o;
}

/* ------- selective scan: 1 warp per (b,d); lane owns n=2l,2l+1; depth-2 -- */
__global__ __launch_bounds__(256) void scan_kernel(
    const float* __restrict__ A_log, const float* __restrict__ D_skip) {
    int warp = (blockIdx.x * blockDim.x + threadIdx.x) >> 5;
    int lane = threadIdx.x & 31;
    if (warp >= B_SZ * DI) return;
    int b = warp >> 9, d = warp & (DI - 1);

    float2 Al = *(const float2*)(A_log + d * DS + 2 * lane);
    float A0 = -__expf(Al.x);
    float A1 = -__expf(Al.y);
    float Dd = D_skip[d];
    float h0 = 0.f, h1 = 0.f;

    const float* xpB = g_xp + (size_t)(b * LSEQ) * XP_P + DTR + 2 * lane;
    const float* dtp = g_dt + (size_t)(b * LSEQ) * DI + d;
    const float* xmp = g_xm + (size_t)(b * LSEQ) * DI + d;
    const float* zp  = g_xz + (size_t)(b * LSEQ) * (2 * DI) + DI + d;
    float* yp        = g_y  + (size_t)(b * LSEQ) * DI + d;

    /* two prefetch slots: slot0 = even t, slot1 = odd t */
    float2 B0 = *(const float2*)(xpB);
    float2 C0 = *(const float2*)(xpB + DS);
    float  t0dt = dtp[0], t0u = xmp[0], t0z = zp[0];
    float2 B1 = *(const float2*)(xpB + XP_P);
    float2 C1 = *(const float2*)(xpB + XP_P + DS);
    float  t1dt = dtp[DI], t1u = xmp[DI], t1z = zp[2 * DI];

#pragma unroll 1
    for (int t = 0; t < LSEQ; t += 2) {
        /* ---- step t (slot 0) ---- */
        {
            float dtv = t0dt, u = t0u, z = t0z;
            float2 Bv = B0, Cv = C0;
            if (t + 2 < LSEQ) {
                const float* p = xpB + (size_t)(t + 2) * XP_P;
                B0 = *(const float2*)(p);
                C0 = *(const float2*)(p + DS);
                t0dt = dtp[(size_t)(t + 2) * DI];
                t0u  = xmp[(size_t)(t + 2) * DI];
                t0z  = zp[(size_t)(t + 2) * 2 * DI];
            }
            float du = dtv * u;
            h0 = fmaf(__expf(dtv * A0), h0, du * Bv.x);
            h1 = fmaf(__expf(dtv * A1), h1, du * Bv.y);
            float y = warp_sum(fmaf(h1, Cv.y, h0 * Cv.x));
            if (lane == 0)
                yp[(size_t)t * DI] = (y + u * Dd) * siluf(z);
        }
        /* ---- step t+1 (slot 1) ---- */
        {
            float dtv = t1dt, u = t1u, z = t1z;
            float2 Bv = B1, Cv = C1;
            if (t + 3 < LSEQ) {
                const float* p = xpB + (size_t)(t + 3) * XP_P;
                B1 = *(const float2*)(p);
                C1 = *(const float2*)(p + DS);
                t1dt = dtp[(size_t)(t + 3) * DI];
                t1u  = xmp[(size_t)(t + 3) * DI];
                t1z  = zp[(size_t)(t + 3) * 2 * DI];
            }
            float du = dtv * u;
            h0 = fmaf(__expf(dtv * A0), h0, du * Bv.x);
            h1 = fmaf(__expf(dtv * A1), h1, du * Bv.y);
            float y = warp_sum(fmaf(h1, Cv.y, h0 * Cv.x));
            if (lane == 0)
                yp[(size_t)(t + 1) * DI] = (y + u * Dd) * siluf(z);
        }
    }
}

/* --------- residual add + sum of splitK slices + LayerNorm --------------- */
__global__ void ln_kernel(const float* __restrict__ x,
                          const float* __restrict__ gamma,
                          const float* __restrict__ beta,
                          float* __restrict__ out) {
    int row = blockIdx.x;
    int c = threadIdx.x;
    float v = x[(size_t)row * DM + c];
#pragma unroll
    for (int s = 0; s < OSPLIT; s++)
        v += g_o[(size_t)s * MROWS * DM + (size_t)row * DM + c];

    float sum  = warp_sum(v);
    float sum2 = warp_sum(v * v);
    __shared__ float ws[8], ws2[8];
    int w = c >> 5, lane = c & 31;
    if (lane == 0) { ws[w] = sum; ws2[w] = sum2; }
    __syncthreads();
    float tot = 0.f, tot2 = 0.f;
#pragma unroll
    for (int i = 0; i < 8; i++) { tot += ws[i]; tot2 += ws2[i]; }
    float mu  = tot * (1.f / DM);
    float var = tot2 * (1.f / DM) - mu * mu;
    out[(size_t)row * DM + c] = (v - mu) * rsqrtf(var + 1e-12f) * gamma[c] + beta[c];
}

/* ---------------- launch --------------------------------------------------*/
extern "C" void kernel_launch(void* const* d_in, const int* in_sizes, int n_in,
                              void* d_out, int out_size) {
    const float* x         = (const float*)d_in[0];
    const float* cos_phi   = (const float*)d_in[1];
    const float* sin_phi   = (const float*)d_in[2];
    const float* delta_mag = (const float*)d_in[3];
    const float* W_in      = (const float*)d_in[4];
    const float* conv_w    = (const float*)d_in[5];
    const float* conv_b    = (const float*)d_in[6];
    const float* W_x       = (const float*)d_in[7];
    const float* W_dt      = (const float*)d_in[8];
    const float* b_dt      = (const float*)d_in[9];
    const float* A_log     = (const float*)d_in[10];
    const float* D_skip    = (const float*)d_in[11];
    const float* W_out     = (const float*)d_in[12];
    const float* gamma     = (const float*)d_in[13];
    const float* beta      = (const float*)d_in[14];
    const float* W_phase   = (const float*)d_in[15];
    float* out = (float*)d_out;

    float* pxz; cudaGetSymbolAddress((void**)&pxz, g_xz);
    float* pxm; cudaGetSymbolAddress((void**)&pxm, g_xm);
    float* pxp; cudaGetSymbolAddress((void**)&pxp, g_xp);
    float* py;  cudaGetSymbolAddress((void**)&py,  g_y);
    float* po;  cudaGetSymbolAddress((void**)&po,  g_o);

    /* 1) xz = x @ W_in : 1600x256 @ 256x1024 (400 blocks) */
    gemm64_kernel<false,false><<<dim3(16, 25, 1), 256>>>(
        x, DM, W_in, 2 * DI, pxz, 2 * DI, 2 * DI, DM, 0,
        nullptr, nullptr, nullptr);

    /* 2) depthwise causal conv + SiLU -> g_xm */
    conv_silu_kernel<<<(MROWS * DI + 255) / 256, 256>>>(conv_w, conv_b);

    /* 3) xp = x_m @ W_x (N=144, padded) + fused phase add on C cols */
    gemm64_kernel<true,true><<<dim3(3, 25, 1), 256>>>(
        pxm, DI, W_x, XP_N, pxp, XP_P, XP_N, DI, 0,
        cos_phi, sin_phi, W_phase);

    /* 4) dt (2 rows per block, 4 d per thread) */
    dt_kernel<<<MROWS / 2, 256>>>(W_dt, b_dt, delta_mag);

    /* 5) selective scan + D-skip + z-gate -> g_y */
    scan_kernel<<<(B_SZ * DI * 32 + 255) / 256, 256>>>(A_log, D_skip);

    /* 6) g_o slices = g_y @ W_out, splitK=4 (400 blocks) */
    gemm64_kernel<false,false><<<dim3(4, 25, OSPLIT), 256>>>(
        py, DI, W_out, DM, po, DM, DM, DI / OSPLIT, MROWS * DM,
        nullptr, nullptr, nullptr);

    /* 7) residual + slice-sum + LayerNorm -> out */
    ln_kernel<<<MROWS, DM>>>(x, gamma, beta, out);
}

// round 4
// speedup vs baseline: 1.5427x; 1.0216x over previous
#include <cuda_runtime.h>
#include <math.h>

#define B_SZ 8
#define LSEQ 200
#define DM   256
#define DI   512
#define DS   64
#define DTR  16
#define NB   4
#define MROWS (B_SZ*LSEQ)      /* 1600 */
#define XP_N  (DTR + 2*DS)     /* 144 real columns  */
#define XP_P  192              /* padded stride     */
#define OSPLIT 4               /* splitK for the out GEMM */

/* ---------------- scratch (device globals; no runtime allocation) -------- */
__device__ float g_xz[MROWS * 2 * DI];        /* x @ W_in                    */
__device__ float g_xm[MROWS * DI];            /* conv+silu(x_m)              */
__device__ float g_xp[MROWS * XP_P];          /* x_m @ W_x (+phase), padded  */
__device__ float g_dt[MROWS * DI];            /* dt                          */
__device__ float g_y [MROWS * DI];            /* scan output, gated          */
__device__ float g_o [OSPLIT * MROWS * DM];   /* splitK slices of y @ W_out  */

__device__ __forceinline__ float softplusf(float x) {
    return x > 20.f ? x : log1pf(__expf(x));
}
__device__ __forceinline__ float siluf(float x) {
    return x / (1.f + __expf(-x));
}
__device__ __forceinline__ float warp_sum(float v) {
#pragma unroll
    for (int o = 16; o; o >>= 1) v += __shfl_xor_sync(0xffffffffu, v, o);
    return v;
}

/* ------------- 64x64x16 fp32 GEMM, double-buffered, splitK-aware --------- */
template<bool GUARDN, bool PHASE>
__global__ __launch_bounds__(256) void gemm64_kernel(
    const float* __restrict__ A, int lda,
    const float* __restrict__ B, int ldb,
    float* __restrict__ C, int ldc,
    int N, int kLen, int sliceElems,
    const float* __restrict__ cosp, const float* __restrict__ sinp,
    const float* __restrict__ Wph)
{
    __shared__ float As[2][16][68];
    __shared__ float Bs[2][16][64];

    const int tid = threadIdx.x;
    const int tx = tid & 15, ty = tid >> 4;
    const int rowBase = blockIdx.y * 64;
    const int colBase = blockIdx.x * 64;

    A += (size_t)blockIdx.z * kLen;
    B += (size_t)blockIdx.z * kLen * ldb;
    C += (size_t)blockIdx.z * sliceElems;

    const int arow = tid >> 2;
    const int akq  = (tid & 3) * 4;
    const int bkk  = tid >> 4;
    const int bnq  = (tid & 15) * 4;

    float acc[4][4] = {};
    float4 av, bv;

    auto loadG = [&](int k0) {
        av = *(const float4*)(A + (size_t)(rowBase + arow) * lda + k0 + akq);
        if (!GUARDN) {
            bv = *(const float4*)(B + (size_t)(k0 + bkk) * ldb + colBase + bnq);
        } else {
            const float* br = B + (size_t)(k0 + bkk) * ldb;
            int gc = colBase + bnq;
            bv.x = (gc + 0 < N) ? br[gc + 0] : 0.f;
            bv.y = (gc + 1 < N) ? br[gc + 1] : 0.f;
            bv.z = (gc + 2 < N) ? br[gc + 2] : 0.f;
            bv.w = (gc + 3 < N) ? br[gc + 3] : 0.f;
        }
    };
    auto stageS = [&](int s) {
        As[s][akq + 0][arow] = av.x;
        As[s][akq + 1][arow] = av.y;
        As[s][akq + 2][arow] = av.z;
        As[s][akq + 3][arow] = av.w;
        *(float4*)&Bs[s][bkk][bnq] = bv;
    };

    const int nt = kLen / 16;
    loadG(0);
    stageS(0);
    __syncthreads();

    for (int kt = 0; kt < nt; kt++) {
        const int cur = kt & 1;
        if (kt + 1 < nt) loadG((kt + 1) * 16);
#pragma unroll
        for (int kk = 0; kk < 16; kk++) {
            float4 a4 = *(const float4*)&As[cur][kk][ty * 4];
            float4 b4 = *(const float4*)&Bs[cur][kk][tx * 4];
            float ar[4] = {a4.x, a4.y, a4.z, a4.w};
            float br[4] = {b4.x, b4.y, b4.z, b4.w};
#pragma unroll
            for (int i = 0; i < 4; i++)
#pragma unroll
                for (int j = 0; j < 4; j++) acc[i][j] += ar[i] * br[j];
        }
        if (kt + 1 < nt) stageS(cur ^ 1);
        __syncthreads();
    }

    const bool doph = PHASE && (colBase + 63 >= DTR + DS) && (colBase < XP_N);

#pragma unroll
    for (int i = 0; i < 4; i++) {
        int r = rowBase + ty * 4 + i;
        float ph[8];
        if (doph) {
            int bb = r / LSEQ, l = r % LSEQ;
#pragma unroll
            for (int jb = 0; jb < NB; jb++) {
                ph[jb]      = cosp[(bb * NB + jb) * LSEQ + l];
                ph[NB + jb] = sinp[(bb * NB + jb) * LSEQ + l];
            }
        }
#pragma unroll
        for (int j = 0; j < 4; j++) {
            int c = colBase + tx * 4 + j;
            float v = acc[i][j];
            if (doph && c >= (DTR + DS) && c < XP_N) {
                int n = c - (DTR + DS);
#pragma unroll
                for (int q = 0; q < 2 * NB; q++) v += ph[q] * Wph[q * DS + n];
            }
            C[(size_t)r * ldc + c] = v;
        }
    }
}

/* ---------------- depthwise causal conv (k=4) + SiLU --------------------- */
__global__ void conv_silu_kernel(const float* __restrict__ conv_w,
                                 const float* __restrict__ conv_b) {
    int idx = blockIdx.x * blockDim.x + threadIdx.x;
    if (idx >= MROWS * DI) return;
    int d = idx % DI;
    int l = (idx / DI) % LSEQ;
    int b = idx / (DI * LSEQ);
    float4 cw = *(const float4*)(conv_w + d * 4);
    float w[4] = {cw.x, cw.y, cw.z, cw.w};
    float acc = conv_b[d];
#pragma unroll
    for (int k = 0; k < 4; k++) {
        int li = l - 3 + k;
        if (li >= 0)
            acc += w[k] * g_xz[(size_t)(b * LSEQ + li) * (2 * DI) + d];
    }
    g_xm[idx] = siluf(acc);
}

/* -------- dt = softplus(dt_lr@W_dt + b)*(1+softplus(dmm)), 8 d per thread -*/
__global__ __launch_bounds__(256) void dt_kernel(
    const float* __restrict__ W_dt, const float* __restrict__ b_dt,
    const float* __restrict__ delta_mag) {
    /* block = 4 rows (64 threads/row); thread handles 8 consecutive d */
    int row = blockIdx.x * 4 + (threadIdx.x >> 6);
    int d0  = (threadIdx.x & 63) * 8;
    int b = row / LSEQ, l = row % LSEQ;

    float dl[DTR];
    {
        const float4* p = (const float4*)(g_xp + (size_t)row * XP_P);
#pragma unroll
        for (int q = 0; q < DTR / 4; q++) {
            float4 v = p[q];
            dl[q * 4 + 0] = v.x; dl[q * 4 + 1] = v.y;
            dl[q * 4 + 2] = v.z; dl[q * 4 + 3] = v.w;
        }
    }
    float4 acc0 = *(const float4*)(b_dt + d0);
    float4 acc1 = *(const float4*)(b_dt + d0 + 4);
#pragma unroll
    for (int r = 0; r < DTR; r++) {
        float4 w0 = *(const float4*)(W_dt + r * DI + d0);
        float4 w1 = *(const float4*)(W_dt + r * DI + d0 + 4);
        acc0.x += dl[r] * w0.x;  acc0.y += dl[r] * w0.y;
        acc0.z += dl[r] * w0.z;  acc0.w += dl[r] * w0.w;
        acc1.x += dl[r] * w1.x;  acc1.y += dl[r] * w1.y;
        acc1.z += dl[r] * w1.z;  acc1.w += dl[r] * w1.w;
    }
    float dmm = 0.25f * (delta_mag[(b * NB + 0) * LSEQ + l] +
                         delta_mag[(b * NB + 1) * LSEQ + l] +
                         delta_mag[(b * NB + 2) * LSEQ + l] +
                         delta_mag[(b * NB + 3) * LSEQ + l]);
    float scale = 1.f + softplusf(dmm);
    float4 o0, o1;
    o0.x = softplusf(acc0.x) * scale;  o0.y = softplusf(acc0.y) * scale;
    o0.z = softplusf(acc0.z) * scale;  o0.w = softplusf(acc0.w) * scale;
    o1.x = softplusf(acc1.x) * scale;  o1.y = softplusf(acc1.y) * scale;
    o1.z = softplusf(acc1.z) * scale;  o1.w = softplusf(acc1.w) * scale;
    *(float4*)(g_dt + (size_t)row * DI + d0)     = o0;
    *(float4*)(g_dt + (size_t)row * DI + d0 + 4) = o1;
}

/* ------- selective scan: 1 warp per (b, d-pair); B/C shared across pair -- */
/* lane owns n = 2*lane, 2*lane+1 for BOTH d's of the pair.                  */
__global__ __launch_bounds__(256) void scan_kernel(
    const float* __restrict__ A_log, const float* __restrict__ D_skip) {
    int warp = (blockIdx.x * blockDim.x + threadIdx.x) >> 5;
    int lane = threadIdx.x & 31;
    int b  = warp >> 8;              /* 256 d-pairs per batch */
    int d0 = (warp & 255) * 2;

    float2 a0 = *(const float2*)(A_log + (size_t)d0 * DS + 2 * lane);
    float2 a1 = *(const float2*)(A_log + (size_t)(d0 + 1) * DS + 2 * lane);
    float A00 = -__expf(a0.x), A01 = -__expf(a0.y);
    float A10 = -__expf(a1.x), A11 = -__expf(a1.y);
    float2 Dd = *(const float2*)(D_skip + d0);

    float h00 = 0.f, h01 = 0.f, h10 = 0.f, h11 = 0.f;

    const float* xpB = g_xp + (size_t)(b * LSEQ) * XP_P + DTR + 2 * lane;
    const float* dtp = g_dt + (size_t)(b * LSEQ) * DI + d0;
    const float* xmp = g_xm + (size_t)(b * LSEQ) * DI + d0;
    const float* zp  = g_xz + (size_t)(b * LSEQ) * (2 * DI) + DI + d0;
    float* yp        = g_y  + (size_t)(b * LSEQ) * DI + d0;

    /* two prefetch slots (even / odd t) */
    float2 B0 = *(const float2*)(xpB);
    float2 C0 = *(const float2*)(xpB + DS);
    float2 dt0 = *(const float2*)(dtp);
    float2 u0  = *(const float2*)(xmp);
    float2 z0  = *(const float2*)(zp);
    float2 B1 = *(const float2*)(xpB + XP_P);
    float2 C1 = *(const float2*)(xpB + XP_P + DS);
    float2 dt1 = *(const float2*)(dtp + DI);
    float2 u1  = *(const float2*)(xmp + DI);
    float2 z1  = *(const float2*)(zp + 2 * DI);

#pragma unroll 1
    for (int t = 0; t < LSEQ; t += 2) {
        /* ---- step t (slot 0) ---- */
        {
            float2 dtv = dt0, u = u0, z = z0, Bv = B0, Cv = C0;
            if (t + 2 < LSEQ) {
                const float* p = xpB + (size_t)(t + 2) * XP_P;
                B0 = *(const float2*)(p);
                C0 = *(const float2*)(p + DS);
                dt0 = *(const float2*)(dtp + (size_t)(t + 2) * DI);
                u0  = *(const float2*)(xmp + (size_t)(t + 2) * DI);
                z0  = *(const float2*)(zp  + (size_t)(t + 2) * 2 * DI);
            }
            float e00 = __expf(dtv.x * A00), e01 = __expf(dtv.x * A01);
            float e10 = __expf(dtv.y * A10), e11 = __expf(dtv.y * A11);
            float du0 = dtv.x * u.x, du1 = dtv.y * u.y;
            h00 = fmaf(e00, h00, du0 * Bv.x);
            h01 = fmaf(e01, h01, du0 * Bv.y);
            h10 = fmaf(e10, h10, du1 * Bv.x);
            h11 = fmaf(e11, h11, du1 * Bv.y);
            float p0 = fmaf(h01, Cv.y, h00 * Cv.x);
            float p1 = fmaf(h11, Cv.y, h10 * Cv.x);
#pragma unroll
            for (int o = 16; o; o >>= 1) {
                p0 += __shfl_xor_sync(0xffffffffu, p0, o);
                p1 += __shfl_xor_sync(0xffffffffu, p1, o);
            }
            if (lane == 0) {
                float2 yv;
                yv.x = (p0 + u.x * Dd.x) * siluf(z.x);
                yv.y = (p1 + u.y * Dd.y) * siluf(z.y);
                *(float2*)(yp + (size_t)t * DI) = yv;
            }
        }
        /* ---- step t+1 (slot 1) ---- */
        {
            float2 dtv = dt1, u = u1, z = z1, Bv = B1, Cv = C1;
            if (t + 3 < LSEQ) {
                const float* p = xpB + (size_t)(t + 3) * XP_P;
                B1 = *(const float2*)(p);
                C1 = *(const float2*)(p + DS);
                dt1 = *(const float2*)(dtp + (size_t)(t + 3) * DI);
                u1  = *(const float2*)(xmp + (size_t)(t + 3) * DI);
                z1  = *(const float2*)(zp  + (size_t)(t + 3) * 2 * DI);
            }
            float e00 = __expf(dtv.x * A00), e01 = __expf(dtv.x * A01);
            float e10 = __expf(dtv.y * A10), e11 = __expf(dtv.y * A11);
            float du0 = dtv.x * u.x, du1 = dtv.y * u.y;
            h00 = fmaf(e00, h00, du0 * Bv.x);
            h01 = fmaf(e01, h01, du0 * Bv.y);
            h10 = fmaf(e10, h10, du1 * Bv.x);
            h11 = fmaf(e11, h11, du1 * Bv.y);
            float p0 = fmaf(h01, Cv.y, h00 * Cv.x);
            float p1 = fmaf(h11, Cv.y, h10 * Cv.x);
#pragma unroll
            for (int o = 16; o; o >>= 1) {
                p0 += __shfl_xor_sync(0xffffffffu, p0, o);
                p1 += __shfl_xor_sync(0xffffffffu, p1, o);
            }
            if (lane == 0) {
                float2 yv;
                yv.x = (p0 + u.x * Dd.x) * siluf(z.x);
                yv.y = (p1 + u.y * Dd.y) * siluf(z.y);
                *(float2*)(yp + (size_t)(t + 1) * DI) = yv;
            }
        }
    }
}

/* --------- residual add + sum of splitK slices + LayerNorm --------------- */
__global__ void ln_kernel(const float* __restrict__ x,
                          const float* __restrict__ gamma,
                          const float* __restrict__ beta,
                          float* __restrict__ out) {
    int row = blockIdx.x;
    int c = threadIdx.x;
    float v = x[(size_t)row * DM + c];
#pragma unroll
    for (int s = 0; s < OSPLIT; s++)
        v += g_o[(size_t)s * MROWS * DM + (size_t)row * DM + c];

    float sum  = warp_sum(v);
    float sum2 = warp_sum(v * v);
    __shared__ float ws[8], ws2[8];
    int w = c >> 5, lane = c & 31;
    if (lane == 0) { ws[w] = sum; ws2[w] = sum2; }
    __syncthreads();
    float tot = 0.f, tot2 = 0.f;
#pragma unroll
    for (int i = 0; i < 8; i++) { tot += ws[i]; tot2 += ws2[i]; }
    float mu  = tot * (1.f / DM);
    float var = tot2 * (1.f / DM) - mu * mu;
    out[(size_t)row * DM + c] = (v - mu) * rsqrtf(var + 1e-12f) * gamma[c] + beta[c];
}

/* ---------------- launch --------------------------------------------------*/
extern "C" void kernel_launch(void* const* d_in, const int* in_sizes, int n_in,
                              void* d_out, int out_size) {
    const float* x         = (const float*)d_in[0];
    const float* cos_phi   = (const float*)d_in[1];
    const float* sin_phi   = (const float*)d_in[2];
    const float* delta_mag = (const float*)d_in[3];
    const float* W_in      = (const float*)d_in[4];
    const float* conv_w    = (const float*)d_in[5];
    const float* conv_b    = (const float*)d_in[6];
    const float* W_x       = (const float*)d_in[7];
    const float* W_dt      = (const float*)d_in[8];
    const float* b_dt      = (const float*)d_in[9];
    const float* A_log     = (const float*)d_in[10];
    const float* D_skip    = (const float*)d_in[11];
    const float* W_out     = (const float*)d_in[12];
    const float* gamma     = (const float*)d_in[13];
    const float* beta      = (const float*)d_in[14];
    const float* W_phase   = (const float*)d_in[15];
    float* out = (float*)d_out;

    float* pxz; cudaGetSymbolAddress((void**)&pxz, g_xz);
    float* pxm; cudaGetSymbolAddress((void**)&pxm, g_xm);
    float* pxp; cudaGetSymbolAddress((void**)&pxp, g_xp);
    float* py;  cudaGetSymbolAddress((void**)&py,  g_y);
    float* po;  cudaGetSymbolAddress((void**)&po,  g_o);

    /* 1) xz = x @ W_in : 1600x256 @ 256x1024 */
    gemm64_kernel<false,false><<<dim3(16, 25, 1), 256>>>(
        x, DM, W_in, 2 * DI, pxz, 2 * DI, 2 * DI, DM, 0,
        nullptr, nullptr, nullptr);

    /* 2) depthwise causal conv + SiLU -> g_xm */
    conv_silu_kernel<<<(MROWS * DI + 255) / 256, 256>>>(conv_w, conv_b);

    /* 3) xp = x_m @ W_x (N=144, padded) + fused phase add on C cols */
    gemm64_kernel<true,true><<<dim3(3, 25, 1), 256>>>(
        pxm, DI, W_x, XP_N, pxp, XP_P, XP_N, DI, 0,
        cos_phi, sin_phi, W_phase);

    /* 4) dt (4 rows per block, 8 d per thread) */
    dt_kernel<<<MROWS / 4, 256>>>(W_dt, b_dt, delta_mag);

    /* 5) selective scan (warp per d-pair) + D-skip + z-gate -> g_y */
    scan_kernel<<<(B_SZ * (DI / 2) * 32) / 256, 256>>>(A_log, D_skip);

    /* 6) g_o slices = g_y @ W_out, splitK=4 */
    gemm64_kernel<false,false><<<dim3(4, 25, OSPLIT), 256>>>(
        py, DI, W_out, DM, po, DM, DM, DI / OSPLIT, MROWS * DM,
        nullptr, nullptr, nullptr);

    /* 7) residual + slice-sum + LayerNorm -> out */
    ln_kernel<<<MROWS, DM>>>(x, gamma, beta, out);
}